// round 1
// baseline (speedup 1.0000x reference)
#include <cuda_runtime.h>
#include <math.h>

#define NB 4
#define NC 64
#define NO 64
#define NH 128
#define NW 128
#define HW (NH*NW)

// Scratch (static device globals — no allocation)
__device__ float g_xT[NB*16*HW*4];      // x repacked: [b][c/4][h][w][4]
__device__ float g_py[NB*9*HW];         // sample y coord per (b,k,h,w)
__device__ float g_px[NB*9*HW];         // sample x coord
__device__ float g_ms[NB*9*HW];         // sigmoid(mask)
__device__ float g_Wt[9*64*64];         // weight repacked: [k][c][o]
__device__ float g_omwT[9*64*28];       // om_weight repacked: [tap][c][j(pad28)]

// ---------------------------------------------------------------------------
// Kernel 0: NCHW -> [b][c/4][h][w][4] repack (coalesced via smem tile)
// grid: 2048 = b(4) * h(128) * wchunk(4), block 256
// ---------------------------------------------------------------------------
__global__ void __launch_bounds__(256) k_transpose(const float* __restrict__ x) {
    __shared__ float ts[64][33];
    int blk = blockIdx.x;
    int wc = blk & 3;
    int h  = (blk >> 2) & 127;
    int b  = blk >> 9;
    int w0 = wc * 32;
    int t = threadIdx.x;
    #pragma unroll
    for (int i = 0; i < 8; i++) {
        int idx = i * 256 + t;
        int c = idx >> 5, w = idx & 31;
        ts[c][w] = x[((b*64 + c)*NH + h)*NW + w0 + w];
    }
    __syncthreads();
    #pragma unroll
    for (int i = 0; i < 8; i++) {
        int idx = i * 256 + t;
        int comp = idx & 3, w = (idx >> 2) & 31, cg = idx >> 7;
        g_xT[((((b*16 + cg)*NH + h)*NW + w0 + w) << 2) + comp] = ts[cg*4 + comp][w];
    }
}

// ---------------------------------------------------------------------------
// Kernel R: weight reorganizations. grid 144 x 256 (36864 threads)
// ---------------------------------------------------------------------------
__global__ void __launch_bounds__(256) k_reorg(const float* __restrict__ wgt,
                                               const float* __restrict__ omw) {
    int i = blockIdx.x * 256 + threadIdx.x;
    if (i < 9*64*64) {              // g_Wt[k][c][o] = weight[o][c][k]
        int o = i & 63, c = (i >> 6) & 63, k = i >> 12;
        g_Wt[i] = wgt[(o*64 + c)*9 + k];
    }
    if (i < 9*64*28) {              // g_omwT[tap][c][j] = om_weight[j][c][tap]
        int j = i % 28;
        int c = (i / 28) & 63;
        int tap = i / (28*64);
        g_omwT[i] = (j < 27) ? omw[(j*64 + c)*9 + tap] : 0.f;
    }
}

// ---------------------------------------------------------------------------
// Kernel 1: offset/mask conv (64 -> 27ch 3x3) + coord precompute.
// 2 horizontally adjacent pixels per thread. 128 blocks x 256 threads.
// Dynamic smem: 9*64*28 floats = 64512 B of repacked om weights.
// ---------------------------------------------------------------------------
__global__ void __launch_bounds__(256) k_offsets(const float* __restrict__ om_bias) {
    extern __shared__ float wsm[];      // [tap][c][28]
    int t = threadIdx.x;
    for (int i = t; i < 9*64*28; i += 256) wsm[i] = g_omwT[i];
    __syncthreads();

    int lin = blockIdx.x * 256 + t;     // 0..32767 (pixel pairs)
    int w0 = (lin & 63) * 2;
    int h  = (lin >> 6) & 127;
    int b  = lin >> 13;

    float4 acc0[7], acc1[7];
    #pragma unroll
    for (int j4 = 0; j4 < 7; j4++) {
        float bv[4];
        #pragma unroll
        for (int q = 0; q < 4; q++) {
            int j = j4*4 + q;
            bv[q] = (j < 27) ? __ldg(om_bias + j) : 0.f;
        }
        acc0[j4] = make_float4(bv[0], bv[1], bv[2], bv[3]);
        acc1[j4] = acc0[j4];
    }

    #pragma unroll
    for (int tap = 0; tap < 9; tap++) {
        int ny  = h + tap/3 - 1;
        int nx0 = w0 + tap%3 - 1;
        bool vy = (ny >= 0) && (ny < NH);
        bool v0 = vy && (nx0 >= 0) && (nx0 < NW);
        bool v1 = vy && (nx0 + 1 >= 0) && (nx0 + 1 < NW);
        #pragma unroll
        for (int cg = 0; cg < 16; cg++) {
            float4 p0 = make_float4(0.f,0.f,0.f,0.f);
            float4 p1 = make_float4(0.f,0.f,0.f,0.f);
            if (v0) p0 = *(const float4*)(g_xT + ((((b*16 + cg)*NH + ny)*NW + nx0) << 2));
            if (v1) p1 = *(const float4*)(g_xT + ((((b*16 + cg)*NH + ny)*NW + nx0 + 1) << 2));
            float p0a[4], p1a[4];
            *(float4*)p0a = p0; *(float4*)p1a = p1;
            const float* wr = &wsm[(tap*64 + cg*4)*28];
            #pragma unroll
            for (int ci = 0; ci < 4; ci++) {
                float a0 = p0a[ci], a1 = p1a[ci];
                #pragma unroll
                for (int j4 = 0; j4 < 7; j4++) {
                    float4 w4 = *(const float4*)(wr + ci*28 + j4*4);
                    acc0[j4].x += a0*w4.x; acc0[j4].y += a0*w4.y;
                    acc0[j4].z += a0*w4.z; acc0[j4].w += a0*w4.w;
                    acc1[j4].x += a1*w4.x; acc1[j4].y += a1*w4.y;
                    acc1[j4].z += a1*w4.z; acc1[j4].w += a1*w4.w;
                }
            }
        }
    }

    float o0[28], o1[28];
    #pragma unroll
    for (int j4 = 0; j4 < 7; j4++) {
        ((float4*)o0)[j4] = acc0[j4];
        ((float4*)o1)[j4] = acc1[j4];
    }

    #pragma unroll
    for (int k = 0; k < 9; k++) {
        int off = ((b*9 + k)*NH + h)*NW + w0;
        float ky = (float)(k/3), kx = (float)(k%3);
        g_py[off]     = o0[2*k]   + ky + (float)(h - 1);
        g_py[off + 1] = o1[2*k]   + ky + (float)(h - 1);
        g_px[off]     = o0[2*k+1] + kx + (float)(w0 - 1);
        g_px[off + 1] = o1[2*k+1] + kx + (float)(w0);
        g_ms[off]     = 1.f / (1.f + expf(-o0[18+k]));
        g_ms[off + 1] = 1.f / (1.f + expf(-o1[18+k]));
    }
}

// ---------------------------------------------------------------------------
// Kernel 2: bilinear sampling + output GEMM.
// One block per (b,h) row: 512 blocks x 256 threads.
// Per tap: phase A fills samp[64c][128px] in smem; phase B does the
// 64x64 x 64x128 outer-product GEMM (8o x 4px register tile per thread).
// ---------------------------------------------------------------------------
__global__ void __launch_bounds__(256) k_main(const float* __restrict__ bias,
                                              float* __restrict__ out) {
    __shared__ float ssamp[64*128];     // 32 KB: [c][px]
    int t = threadIdx.x;
    int blk = blockIdx.x;
    int h = blk & 127;
    int b = blk >> 7;
    int o_base  = (t >> 5) * 8;
    int px_base = (t & 31) * 4;

    float4 acc[8];
    #pragma unroll
    for (int i = 0; i < 8; i++) acc[i] = make_float4(0.f,0.f,0.f,0.f);

    for (int k = 0; k < 9; k++) {
        __syncthreads();
        int offm = ((b*9 + k)*NH + h)*NW;
        // ---- phase A: build samp tile ----
        #pragma unroll
        for (int it = 0; it < 8; it++) {
            int lin = it*256 + t;
            int px = lin & 127;
            int cg = lin >> 7;               // 0..15
            float py  = __ldg(g_py + offm + px);
            float pxx = __ldg(g_px + offm + px);
            float m   = __ldg(g_ms + offm + px);
            float y0f = floorf(py), x0f = floorf(pxx);
            float wy = py - y0f, wx = pxx - x0f;
            bool vy0 = (y0f >=  0.f) && (y0f <= 127.f);
            bool vy1 = (y0f >= -1.f) && (y0f <= 126.f);
            bool vx0 = (x0f >=  0.f) && (x0f <= 127.f);
            bool vx1 = (x0f >= -1.f) && (x0f <= 126.f);
            int iy0 = (int)fminf(fmaxf(y0f,       0.f), 127.f);
            int iy1 = (int)fminf(fmaxf(y0f + 1.f, 0.f), 127.f);
            int ix0 = (int)fminf(fmaxf(x0f,       0.f), 127.f);
            int ix1 = (int)fminf(fmaxf(x0f + 1.f, 0.f), 127.f);
            float w00 = (1.f-wy)*(1.f-wx) * ((vy0 && vx0) ? m : 0.f);
            float w01 = (1.f-wy)*wx       * ((vy0 && vx1) ? m : 0.f);
            float w10 = wy*(1.f-wx)       * ((vy1 && vx0) ? m : 0.f);
            float w11 = wy*wx             * ((vy1 && vx1) ? m : 0.f);
            const float* cb = g_xT + (((size_t)(b*16 + cg))*HW << 2);
            float4 A = *(const float4*)(cb + ((iy0*NW + ix0) << 2));
            float4 Bc= *(const float4*)(cb + ((iy0*NW + ix1) << 2));
            float4 Cc= *(const float4*)(cb + ((iy1*NW + ix0) << 2));
            float4 D = *(const float4*)(cb + ((iy1*NW + ix1) << 2));
            float vx_ = w00*A.x + w01*Bc.x + w10*Cc.x + w11*D.x;
            float vy_ = w00*A.y + w01*Bc.y + w10*Cc.y + w11*D.y;
            float vz_ = w00*A.z + w01*Bc.z + w10*Cc.z + w11*D.z;
            float vw_ = w00*A.w + w01*Bc.w + w10*Cc.w + w11*D.w;
            int sb = (cg*4)*128 + px;
            ssamp[sb]       = vx_;
            ssamp[sb + 128] = vy_;
            ssamp[sb + 256] = vz_;
            ssamp[sb + 384] = vw_;
        }
        __syncthreads();
        // ---- phase B: out[o] += W[k][c][o] * samp[c][px] ----
        const float* wk = g_Wt + k*4096 + o_base;
        #pragma unroll 4
        for (int c = 0; c < 64; c++) {
            float4 wlo = __ldg((const float4*)(wk + c*64));
            float4 whi = __ldg((const float4*)(wk + c*64 + 4));
            float4 s4  = *(const float4*)(ssamp + c*128 + px_base);
            float wv[8] = {wlo.x, wlo.y, wlo.z, wlo.w, whi.x, whi.y, whi.z, whi.w};
            #pragma unroll
            for (int oi = 0; oi < 8; oi++) {
                acc[oi].x += wv[oi]*s4.x;
                acc[oi].y += wv[oi]*s4.y;
                acc[oi].z += wv[oi]*s4.z;
                acc[oi].w += wv[oi]*s4.w;
            }
        }
    }

    #pragma unroll
    for (int oi = 0; oi < 8; oi++) {
        float bv = __ldg(bias + o_base + oi);
        float4 r = acc[oi];
        r.x += bv; r.y += bv; r.z += bv; r.w += bv;
        *(float4*)(out + (((b*64 + o_base + oi)*NH + h)*NW) + px_base) = r;
    }
}

// ---------------------------------------------------------------------------
extern "C" void kernel_launch(void* const* d_in, const int* in_sizes, int n_in,
                              void* d_out, int out_size) {
    const float* x         = (const float*)d_in[0];
    const float* weight    = (const float*)d_in[1];
    const float* bias      = (const float*)d_in[2];
    const float* om_weight = (const float*)d_in[3];
    const float* om_bias   = (const float*)d_in[4];
    float* out = (float*)d_out;

    cudaFuncSetAttribute(k_offsets, cudaFuncAttributeMaxDynamicSharedMemorySize, 9*64*28*4);

    k_transpose<<<2048, 256>>>(x);
    k_reorg<<<144, 256>>>(weight, om_weight);
    k_offsets<<<128, 256, 9*64*28*4>>>(om_bias);
    k_main<<<512, 256>>>(bias, out);
}